// round 10
// baseline (speedup 1.0000x reference)
#include <cuda_runtime.h>
#include <cuda_fp16.h>
#include <cstdint>

#define BATCH 16
#define NPTS  4096
#define NOUT  1024
#define CIN   256
#define COUT  512
#define KNB   16
#define XOUT_ELEMS (BATCH * NOUT * COUT)   // 8388608
#define FPS_THREADS 512

// Scratch: device globals (no allocation allowed anywhere).
__device__ __half g_h[(size_t)BATCH * NPTS * COUT];  // 64 MB: post-MLP features (fp16)
__device__ int    g_fid[BATCH * NOUT];               // flat FPS indices into B*N

// ---------------- packed f32x2 helpers (bit-exact per-lane .rn) ----------------
static __device__ __forceinline__ unsigned long long pk2(float a, float b) {
    unsigned long long r;
    asm("mov.b64 %0,{%1,%2};" : "=l"(r) : "f"(a), "f"(b));
    return r;
}
static __device__ __forceinline__ void upk2(unsigned long long v, float& a, float& b) {
    asm("mov.b64 {%0,%1},%2;" : "=f"(a), "=f"(b) : "l"(v));
}
static __device__ __forceinline__ unsigned long long addx2(unsigned long long a, unsigned long long b) {
    unsigned long long r;
    asm("add.rn.f32x2 %0,%1,%2;" : "=l"(r) : "l"(a), "l"(b));
    return r;
}
static __device__ __forceinline__ unsigned long long mulx2(unsigned long long a, unsigned long long b) {
    unsigned long long r;
    asm("mul.rn.f32x2 %0,%1,%2;" : "=l"(r) : "l"(a), "l"(b));
    return r;
}
static __device__ __forceinline__ uint32_t f2tf32(float f) {
    uint32_t r;
    asm("cvt.rna.tf32.f32 %0,%1;" : "=r"(r) : "f"(f));
    return r;
}
static __device__ __forceinline__ void mma_tf32(float* c, const uint32_t* a, const uint32_t* b) {
    asm volatile(
        "mma.sync.aligned.m16n8k8.row.col.f32.tf32.tf32.f32 "
        "{%0,%1,%2,%3},{%4,%5,%6,%7},{%8,%9},{%0,%1,%2,%3};"
        : "+f"(c[0]), "+f"(c[1]), "+f"(c[2]), "+f"(c[3])
        : "r"(a[0]), "r"(a[1]), "r"(a[2]), "r"(a[3]), "r"(b[0]), "r"(b[1]));
}

// ---------------- FPS: one CTA (512 threads) per batch ----------------
// Distance math bit-identical to the passing kernel: dist = ((dx*dx + dy*dy) + dz*dz),
// all .rn, NO fma contraction; running fmin; first-occurrence argmax.
// R9 changes (semantics-preserving):
//  * in-loop argmax tracking -> fmax tree; index recovered post-loop via
//    equality mask + ffs (off the redux critical path).
//  * cross-warp reduction -> one atomicMax on a 64-bit key:
//       key = (it << 44) | (dist_bits << 12) | (0xFFF ^ point_idx)
//    dist >= 0 so dist_bits are order-monotonic; ties pick lowest idx;
//    the iteration tag is strictly increasing so stale keys always lose
//    (no slot reset needed). Two parity slots make epochs race-free.
static __device__ void fps_block(const float* __restrict__ p, float* __restrict__ out, char* smem)
{
    const int b = blockIdx.x;
    float* s_p = (float*)smem;                  // 4096*3 floats, interleaved xyz
    unsigned long long* s_key = (unsigned long long*)(s_p + 3 * NPTS);  // [2] parity slots

    const float* pb = p + (size_t)b * NPTS * 3;
    const int t = threadIdx.x, lane = t & 31;
    for (int i = t; i < 3 * NPTS; i += FPS_THREADS) s_p[i] = pb[i];
    if (t == 0) { s_key[0] = 0ull; s_key[1] = 0ull; }
    __syncthreads();

    // it = 0 output (forced index 0)
    if (t == 0) {
        g_fid[b * NOUT] = b * NPTS;
        float* po = out + (size_t)XOUT_ELEMS + (size_t)(b * NOUT) * 3;
        po[0] = s_p[0]; po[1] = s_p[1]; po[2] = s_p[2];
    }

    // thread t owns points [t*8, t*8+8), packed in pairs
    const int base = t * 8;
    unsigned long long Px[4], Py[4], Pz[4];
    float d[8];
#pragma unroll
    for (int q = 0; q < 4; ++q) {
        const int j0 = base + 2 * q;
        Px[q] = pk2(s_p[3 * j0 + 0], s_p[3 * j0 + 3]);
        Py[q] = pk2(s_p[3 * j0 + 1], s_p[3 * j0 + 4]);
        Pz[q] = pk2(s_p[3 * j0 + 2], s_p[3 * j0 + 5]);
    }
#pragma unroll
    for (int j = 0; j < 8; ++j) d[j] = __int_as_float(0x7f800000);  // +inf

    float cx = s_p[0], cy = s_p[1], cz = s_p[2];  // center = point 0

    for (int it = 1; it < NOUT; ++it) {
        const unsigned long long nx = pk2(-cx, -cx);
        const unsigned long long ny = pk2(-cy, -cy);
        const unsigned long long nz = pk2(-cz, -cz);
#pragma unroll
        for (int q = 0; q < 4; ++q) {
            unsigned long long dx = addx2(Px[q], nx);
            unsigned long long dy = addx2(Py[q], ny);
            unsigned long long dz = addx2(Pz[q], nz);
            unsigned long long sq =
                addx2(addx2(mulx2(dx, dx), mulx2(dy, dy)), mulx2(dz, dz));
            float s0, s1;
            upk2(sq, s0, s1);
            d[2 * q]     = fminf(d[2 * q], s0);
            d[2 * q + 1] = fminf(d[2 * q + 1], s1);
        }
        // thread-local max via fmax tree (alu-cheap; no index tracking in loop)
        const float m01 = fmaxf(d[0], d[1]), m23 = fmaxf(d[2], d[3]);
        const float m45 = fmaxf(d[4], d[5]), m67 = fmaxf(d[6], d[7]);
        const float bmax = fmaxf(fmaxf(m01, m23), fmaxf(m45, m67));
        const unsigned bb = __float_as_uint(bmax);

        // index recovery: depends only on thread-local state -> overlaps redux latency
        unsigned em = 0;
#pragma unroll
        for (int j = 0; j < 8; ++j) em |= (d[j] == bmax) ? (1u << j) : 0u;
        const int bi = base + __ffs(em) - 1;     // lowest j = first occurrence

        // warp reduction (d >= 0 so float bits are u32-monotonic)
        const unsigned wm = __reduce_max_sync(0xffffffffu, bb);
        const unsigned cand = (bb == wm) ? (0xFFFu ^ (unsigned)bi) : 0u;
        const unsigned wi = __reduce_max_sync(0xffffffffu, cand);  // max(~idx) = min idx

        if (lane == 0) {
            const unsigned long long key =
                ((unsigned long long)it << 44) | ((unsigned long long)wm << 12) | wi;
            atomicMax(&s_key[it & 1], key);
        }
        __syncthreads();   // single barrier per iteration

        const unsigned long long key = s_key[it & 1];
        const int w = 0xFFF ^ (int)(key & 0xFFFull);

        cx = s_p[3 * w];
        cy = s_p[3 * w + 1];
        cz = s_p[3 * w + 2];

        if (t == 0) {
            g_fid[b * NOUT + it] = b * NPTS + w;
            float* po = out + (size_t)XOUT_ELEMS + (size_t)(b * NOUT + it) * 3;
            po[0] = cx; po[1] = cy; po[2] = cz;
        }
    }
}

// ---------------- GEMM: h = ReLU(BN(x @ W^T + b)), tf32 mma.sync, fp16 out ----------------
// CTA tile 128x128, 512 threads = 16 warps (4x4), warp tile 32x32, K-chunk 32.
static __device__ void gemm_block(const float* __restrict__ x, const float* __restrict__ Wm,
                                  const float* __restrict__ bias, const float* __restrict__ gamma,
                                  const float* __restrict__ beta, const float* __restrict__ mean,
                                  const float* __restrict__ var, int g, char* smem)
{
    float* As   = (float*)smem;        // 128 x 36 (padded)
    float* Bs   = As + 128 * 36;       // 128 x 36
    float* s_sc = Bs + 128 * 36;       // 128
    float* s_sh = s_sc + 128;          // 128

    const int m0 = (g >> 2) * 128;     // 512 M-tiles
    const int n0 = (g & 3) * 128;      // 4 N-tiles
    const int t = threadIdx.x, lane = t & 31, warp = t >> 5;
    const int wm = warp >> 2, wn = warp & 3;
    const int grp = lane >> 2, tg = lane & 3;

    if (t < 128) {
        const int c = n0 + t;
        const float sc = gamma[c] * rsqrtf(var[c] + 1e-5f);
        s_sc[t] = sc;
        s_sh[t] = (bias[c] - mean[c]) * sc + beta[c];
    }

    float acc[2][4][4];
#pragma unroll
    for (int mt = 0; mt < 2; ++mt)
#pragma unroll
        for (int nt = 0; nt < 4; ++nt)
#pragma unroll
            for (int j = 0; j < 4; ++j) acc[mt][nt][j] = 0.0f;

    for (int kc = 0; kc < CIN; kc += 32) {
#pragma unroll
        for (int r = 0; r < 2; ++r) {
            const int fi = t + r * 512;
            const int row = fi >> 3, c4 = (fi & 7) * 4;
            const float4 va = *(const float4*)(x + (size_t)(m0 + row) * CIN + kc + c4);
            *(float4*)(As + row * 36 + c4) = va;
            const float4 vb = *(const float4*)(Wm + (size_t)(n0 + row) * CIN + kc + c4);
            *(float4*)(Bs + row * 36 + c4) = vb;
        }
        __syncthreads();
#pragma unroll
        for (int ks = 0; ks < 4; ++ks) {
            const int kb = ks * 8;
            uint32_t a[2][4], bf[4][2];
#pragma unroll
            for (int mt = 0; mt < 2; ++mt) {
                const float* ap = As + (wm * 32 + mt * 16 + grp) * 36 + kb + tg;
                a[mt][0] = f2tf32(ap[0]);
                a[mt][1] = f2tf32(ap[8 * 36]);
                a[mt][2] = f2tf32(ap[4]);
                a[mt][3] = f2tf32(ap[8 * 36 + 4]);
            }
#pragma unroll
            for (int nt = 0; nt < 4; ++nt) {
                const float* bp = Bs + (wn * 32 + nt * 8 + grp) * 36 + kb + tg;
                bf[nt][0] = f2tf32(bp[0]);
                bf[nt][1] = f2tf32(bp[4]);
            }
#pragma unroll
            for (int mt = 0; mt < 2; ++mt)
#pragma unroll
                for (int nt = 0; nt < 4; ++nt) mma_tf32(acc[mt][nt], a[mt], bf[nt]);
        }
        __syncthreads();
    }

    // epilogue: BN(eval) + ReLU -> fp16 (paired cols => half2 stores)
#pragma unroll
    for (int mt = 0; mt < 2; ++mt) {
#pragma unroll
        for (int nt = 0; nt < 4; ++nt) {
#pragma unroll
            for (int rr = 0; rr < 2; ++rr) {   // rr: +0 / +8 row
                const int row = m0 + wm * 32 + mt * 16 + grp + rr * 8;
                const int lc = wn * 32 + nt * 8 + tg * 2;
                float v0 = acc[mt][nt][rr * 2 + 0] * s_sc[lc]     + s_sh[lc];
                float v1 = acc[mt][nt][rr * 2 + 1] * s_sc[lc + 1] + s_sh[lc + 1];
                v0 = fmaxf(v0, 0.0f);
                v1 = fmaxf(v1, 0.0f);
                *(__half2*)(g_h + (size_t)row * COUT + n0 + lc) = __floats2half2_rn(v0, v1);
            }
        }
    }
}

// ---------------- fused kernel: FPS blocks 0..15 (wave 1) + GEMM blocks ----------------
__global__ __launch_bounds__(FPS_THREADS)
void fused_kernel(const float* __restrict__ x, const float* __restrict__ p,
                  const float* __restrict__ Wm, const float* __restrict__ bias,
                  const float* __restrict__ gamma, const float* __restrict__ beta,
                  const float* __restrict__ mean, const float* __restrict__ var,
                  float* __restrict__ out)
{
    extern __shared__ char smem[];
    if (blockIdx.x < 16)
        fps_block(p, out, smem);
    else
        gemm_block(x, Wm, bias, gamma, beta, mean, var, (int)blockIdx.x - 16, smem);
}

// ---------------- gather + maxpool over K neighbors (fp16 h) ----------------
// Rounding to fp16 is monotonic, so max_k rnd(h_k) == rnd(max_k h_k): the only
// error vs fp32 is one fp16 rounding of the final max (<= 2^-11 relative).
// sid_euc is int32 in practice (JAX x64 disabled); deterministic int64 sniff kept.
__global__ __launch_bounds__(64)
void gather_kernel(const int* __restrict__ sid32, float* __restrict__ out)
{
    __shared__ int s_idx[KNB];
    const int r = blockIdx.x;     // output row in [0, B*n)
    const int t = threadIdx.x;    // 0..63, channel group: 8 halves at col t*8
    if (t < KNB) {
        const bool is64 = (sid32[1] == 0) && (sid32[3] == 0) &&
                          (sid32[5] == 0) && (sid32[7] == 0);
        const int fidf = g_fid[r];
        s_idx[t] = is64 ? sid32[((size_t)fidf * KNB + t) * 2]
                        : sid32[(size_t)fidf * KNB + t];
    }
    __syncthreads();

    uint4 v = *(const uint4*)(g_h + (size_t)s_idx[0] * COUT + t * 8);
    __half2 m0 = *(__half2*)&v.x, m1 = *(__half2*)&v.y;
    __half2 m2 = *(__half2*)&v.z, m3 = *(__half2*)&v.w;
#pragma unroll
    for (int k = 1; k < KNB; ++k) {
        v = *(const uint4*)(g_h + (size_t)s_idx[k] * COUT + t * 8);
        m0 = __hmax2(m0, *(__half2*)&v.x);
        m1 = __hmax2(m1, *(__half2*)&v.y);
        m2 = __hmax2(m2, *(__half2*)&v.z);
        m3 = __hmax2(m3, *(__half2*)&v.w);
    }
    const float2 f0 = __half22float2(m0), f1 = __half22float2(m1);
    const float2 f2 = __half22float2(m2), f3 = __half22float2(m3);
    float* o = out + (size_t)r * COUT + t * 8;
    *(float4*)(o)     = make_float4(f0.x, f0.y, f1.x, f1.y);
    *(float4*)(o + 4) = make_float4(f2.x, f2.y, f3.x, f3.y);
}

// ---------------- launch ----------------
// 53.5 KB: FPS fits (49152 pts + 16 key slots), GEMM fits (37888), and GEMM
// keeps 4 CTAs/SM (4 x 53504 = 214016 < 228KB, 4 x 512 = 2048 threads).
#define FUSED_SMEM 53504

extern "C" void kernel_launch(void* const* d_in, const int* in_sizes, int n_in,
                              void* d_out, int out_size)
{
    (void)in_sizes; (void)n_in; (void)out_size;
    const float* x      = (const float*)d_in[0];
    const float* p      = (const float*)d_in[1];
    const int*   sid    = (const int*)d_in[2];   // int32 (x64 disabled in JAX)
    // d_in[3] = tid_euc (unused by reference)
    const float* W      = (const float*)d_in[4];
    const float* bias   = (const float*)d_in[5];
    const float* gamma  = (const float*)d_in[6];
    const float* beta   = (const float*)d_in[7];
    const float* mean   = (const float*)d_in[8];
    const float* var    = (const float*)d_in[9];
    float* out = (float*)d_out;

    // Opt-in to >48KB dynamic smem (host-side, idempotent, capture-legal).
    cudaFuncSetAttribute(fused_kernel, cudaFuncAttributeMaxDynamicSharedMemorySize, FUSED_SMEM);

    const int gemm_blocks = (BATCH * NPTS / 128) * (COUT / 128);  // 2048
    fused_kernel<<<16 + gemm_blocks, FPS_THREADS, FUSED_SMEM>>>(
        x, p, W, bias, gamma, beta, mean, var, out);
    gather_kernel<<<BATCH * NOUT, 64>>>(sid, out);
}

// round 11
// speedup vs baseline: 1.2307x; 1.2307x over previous
#include <cuda_runtime.h>
#include <cuda_fp16.h>
#include <cstdint>

#define BATCH 16
#define NPTS  4096
#define NOUT  1024
#define CIN   256
#define COUT  512
#define KNB   16
#define XOUT_ELEMS (BATCH * NOUT * COUT)   // 8388608
#define FPS_THREADS 512

// Scratch: device globals (no allocation allowed anywhere).
__device__ __half g_h[(size_t)BATCH * NPTS * COUT];  // 64 MB: post-MLP features (fp16)
__device__ int    g_fid[BATCH * NOUT];               // flat FPS indices into B*N

// ---------------- packed f32x2 helpers (bit-exact per-lane .rn) ----------------
static __device__ __forceinline__ unsigned long long pk2(float a, float b) {
    unsigned long long r;
    asm("mov.b64 %0,{%1,%2};" : "=l"(r) : "f"(a), "f"(b));
    return r;
}
static __device__ __forceinline__ void upk2(unsigned long long v, float& a, float& b) {
    asm("mov.b64 {%0,%1},%2;" : "=f"(a), "=f"(b) : "l"(v));
}
static __device__ __forceinline__ unsigned long long addx2(unsigned long long a, unsigned long long b) {
    unsigned long long r;
    asm("add.rn.f32x2 %0,%1,%2;" : "=l"(r) : "l"(a), "l"(b));
    return r;
}
static __device__ __forceinline__ unsigned long long mulx2(unsigned long long a, unsigned long long b) {
    unsigned long long r;
    asm("mul.rn.f32x2 %0,%1,%2;" : "=l"(r) : "l"(a), "l"(b));
    return r;
}
static __device__ __forceinline__ uint32_t f2tf32(float f) {
    uint32_t r;
    asm("cvt.rna.tf32.f32 %0,%1;" : "=r"(r) : "f"(f));
    return r;
}
static __device__ __forceinline__ void mma_tf32(float* c, const uint32_t* a, const uint32_t* b) {
    asm volatile(
        "mma.sync.aligned.m16n8k8.row.col.f32.tf32.tf32.f32 "
        "{%0,%1,%2,%3},{%4,%5,%6,%7},{%8,%9},{%0,%1,%2,%3};"
        : "+f"(c[0]), "+f"(c[1]), "+f"(c[2]), "+f"(c[3])
        : "r"(a[0]), "r"(a[1]), "r"(a[2]), "r"(a[3]), "r"(b[0]), "r"(b[1]));
}

// ---------------- FPS: one CTA (512 threads) per batch ----------------
// Arithmetic/selection bit-identical to the R5/R8 passing kernels:
// dist = ((dx*dx + dy*dy) + dz*dz), all .rn, NO fma contraction; running fmin;
// first-occurrence argmax via strict-> scan + lowest-lane/lowest-warp ties.
// Single barrier per iteration (parity-double-buffered candidate slab).
// R11 tweak: stage 2 speculatively prefetches all 16 candidate centers'
// coords in parallel with the value reduction, then shuffles the winning
// COORDS (removes a dependent LDS+shfl chain from the serial tail).
static __device__ void fps_block(const float* __restrict__ p, float* __restrict__ out, char* smem)
{
    const int b = blockIdx.x;
    float* s_p  = (float*)smem;                 // 4096*3 floats, interleaved xyz
    float* s_rv = s_p + 3 * NPTS;               // [2 parity][16]
    int*   s_ri = (int*)(s_rv + 32);            // [2 parity][16]

    const float* pb = p + (size_t)b * NPTS * 3;
    const int t = threadIdx.x, lane = t & 31, warp = t >> 5;
    for (int i = t; i < 3 * NPTS; i += FPS_THREADS) s_p[i] = pb[i];
    __syncthreads();

    // it = 0 output (forced index 0)
    if (t == 0) {
        g_fid[b * NOUT] = b * NPTS;
        float* po = out + (size_t)XOUT_ELEMS + (size_t)(b * NOUT) * 3;
        po[0] = s_p[0]; po[1] = s_p[1]; po[2] = s_p[2];
    }

    // thread t owns points [t*8, t*8+8), packed in pairs
    const int base = t * 8;
    unsigned long long Px[4], Py[4], Pz[4];
    float d[8];
#pragma unroll
    for (int q = 0; q < 4; ++q) {
        const int j0 = base + 2 * q;
        Px[q] = pk2(s_p[3 * j0 + 0], s_p[3 * j0 + 3]);
        Py[q] = pk2(s_p[3 * j0 + 1], s_p[3 * j0 + 4]);
        Pz[q] = pk2(s_p[3 * j0 + 2], s_p[3 * j0 + 5]);
    }
#pragma unroll
    for (int j = 0; j < 8; ++j) d[j] = __int_as_float(0x7f800000);  // +inf

    float cx = s_p[0], cy = s_p[1], cz = s_p[2];  // center = point 0

    for (int it = 1; it < NOUT; ++it) {
        const int buf = it & 1;
        const unsigned long long nx = pk2(-cx, -cx);
        const unsigned long long ny = pk2(-cy, -cy);
        const unsigned long long nz = pk2(-cz, -cz);
        float best = -1.0f;
        int bi = base;
#pragma unroll
        for (int q = 0; q < 4; ++q) {
            unsigned long long dx = addx2(Px[q], nx);
            unsigned long long dy = addx2(Py[q], ny);
            unsigned long long dz = addx2(Pz[q], nz);
            unsigned long long sq =
                addx2(addx2(mulx2(dx, dx), mulx2(dy, dy)), mulx2(dz, dz));
            float s0, s1;
            upk2(sq, s0, s1);
            float d0 = fminf(d[2 * q], s0);
            float d1 = fminf(d[2 * q + 1], s1);
            d[2 * q] = d0;
            d[2 * q + 1] = d1;
            if (d0 > best) { best = d0; bi = base + 2 * q; }
            if (d1 > best) { best = d1; bi = base + 2 * q + 1; }
        }
        // warp argmax: d >= 0 so float bits are monotonic as u32
        const unsigned bb = __float_as_uint(best);
        const unsigned wm = __reduce_max_sync(0xffffffffu, bb);
        const unsigned msk = __ballot_sync(0xffffffffu, bb == wm);
        const int src = __ffs(msk) - 1;              // lowest lane = lowest point idx
        const int wbi = __shfl_sync(0xffffffffu, bi, src);
        if (lane == 0) {
            s_rv[buf * 16 + warp] = __uint_as_float(wm);
            s_ri[buf * 16 + warp] = wbi;
        }
        __syncthreads();   // single barrier per iteration

        // stage 2: every warp redundantly reduces the 16 per-warp candidates.
        // Speculative center prefetch overlaps the value redux.
        const float* rv = s_rv + buf * 16;
        const int*   ri = s_ri + buf * 16;
        const unsigned v = (lane < 16) ? __float_as_uint(rv[lane]) : 0u;
        const int ril = (lane < 16) ? ri[lane] : 0;
        const float pxl = s_p[3 * ril];
        const float pyl = s_p[3 * ril + 1];
        const float pzl = s_p[3 * ril + 2];
        const unsigned m2 = __reduce_max_sync(0xffffffffu, v);
        const unsigned e2 = __ballot_sync(0xffffffffu, (v == m2) && (lane < 16));
        const int s2 = __ffs(e2) - 1;                // lowest warp = lowest point idx
        cx = __shfl_sync(0xffffffffu, pxl, s2);
        cy = __shfl_sync(0xffffffffu, pyl, s2);
        cz = __shfl_sync(0xffffffffu, pzl, s2);

        // stream outputs (fire-and-forget store by thread 0)
        if (t == 0) {
            const int w = __shfl_sync(0x1u, ril, 0) , _unused = 0; (void)_unused;
            // NOTE: warp 0 lane 0: need winning index w = ri[s2]; recompute via shfl
        }
        if (warp == 0) {
            const int w = __shfl_sync(0xffffffffu, ril, s2);
            if (lane == 0) {
                g_fid[b * NOUT + it] = b * NPTS + w;
                float* po = out + (size_t)XOUT_ELEMS + (size_t)(b * NOUT + it) * 3;
                po[0] = cx; po[1] = cy; po[2] = cz;
            }
        }
    }
}

// ---------------- GEMM: h = ReLU(BN(x @ W^T + b)), tf32 mma.sync, fp16 out ----------------
// CTA tile 128x128, 512 threads = 16 warps (4x4), warp tile 32x32, K-chunk 32.
static __device__ void gemm_block(const float* __restrict__ x, const float* __restrict__ Wm,
                                  const float* __restrict__ bias, const float* __restrict__ gamma,
                                  const float* __restrict__ beta, const float* __restrict__ mean,
                                  const float* __restrict__ var, int g, char* smem)
{
    float* As   = (float*)smem;        // 128 x 36 (padded)
    float* Bs   = As + 128 * 36;       // 128 x 36
    float* s_sc = Bs + 128 * 36;       // 128
    float* s_sh = s_sc + 128;          // 128

    const int m0 = (g >> 2) * 128;     // 512 M-tiles
    const int n0 = (g & 3) * 128;      // 4 N-tiles
    const int t = threadIdx.x, lane = t & 31, warp = t >> 5;
    const int wm = warp >> 2, wn = warp & 3;
    const int grp = lane >> 2, tg = lane & 3;

    if (t < 128) {
        const int c = n0 + t;
        const float sc = gamma[c] * rsqrtf(var[c] + 1e-5f);
        s_sc[t] = sc;
        s_sh[t] = (bias[c] - mean[c]) * sc + beta[c];
    }

    float acc[2][4][4];
#pragma unroll
    for (int mt = 0; mt < 2; ++mt)
#pragma unroll
        for (int nt = 0; nt < 4; ++nt)
#pragma unroll
            for (int j = 0; j < 4; ++j) acc[mt][nt][j] = 0.0f;

    for (int kc = 0; kc < CIN; kc += 32) {
#pragma unroll
        for (int r = 0; r < 2; ++r) {
            const int fi = t + r * 512;
            const int row = fi >> 3, c4 = (fi & 7) * 4;
            const float4 va = *(const float4*)(x + (size_t)(m0 + row) * CIN + kc + c4);
            *(float4*)(As + row * 36 + c4) = va;
            const float4 vb = *(const float4*)(Wm + (size_t)(n0 + row) * CIN + kc + c4);
            *(float4*)(Bs + row * 36 + c4) = vb;
        }
        __syncthreads();
#pragma unroll
        for (int ks = 0; ks < 4; ++ks) {
            const int kb = ks * 8;
            uint32_t a[2][4], bf[4][2];
#pragma unroll
            for (int mt = 0; mt < 2; ++mt) {
                const float* ap = As + (wm * 32 + mt * 16 + grp) * 36 + kb + tg;
                a[mt][0] = f2tf32(ap[0]);
                a[mt][1] = f2tf32(ap[8 * 36]);
                a[mt][2] = f2tf32(ap[4]);
                a[mt][3] = f2tf32(ap[8 * 36 + 4]);
            }
#pragma unroll
            for (int nt = 0; nt < 4; ++nt) {
                const float* bp = Bs + (wn * 32 + nt * 8 + grp) * 36 + kb + tg;
                bf[nt][0] = f2tf32(bp[0]);
                bf[nt][1] = f2tf32(bp[4]);
            }
#pragma unroll
            for (int mt = 0; mt < 2; ++mt)
#pragma unroll
                for (int nt = 0; nt < 4; ++nt) mma_tf32(acc[mt][nt], a[mt], bf[nt]);
        }
        __syncthreads();
    }

    // epilogue: BN(eval) + ReLU -> fp16 (paired cols => half2 stores)
#pragma unroll
    for (int mt = 0; mt < 2; ++mt) {
#pragma unroll
        for (int nt = 0; nt < 4; ++nt) {
#pragma unroll
            for (int rr = 0; rr < 2; ++rr) {   // rr: +0 / +8 row
                const int row = m0 + wm * 32 + mt * 16 + grp + rr * 8;
                const int lc = wn * 32 + nt * 8 + tg * 2;
                float v0 = acc[mt][nt][rr * 2 + 0] * s_sc[lc]     + s_sh[lc];
                float v1 = acc[mt][nt][rr * 2 + 1] * s_sc[lc + 1] + s_sh[lc + 1];
                v0 = fmaxf(v0, 0.0f);
                v1 = fmaxf(v1, 0.0f);
                *(__half2*)(g_h + (size_t)row * COUT + n0 + lc) = __floats2half2_rn(v0, v1);
            }
        }
    }
}

// ---------------- fused kernel: FPS blocks 0..15 (wave 1) + GEMM blocks ----------------
__global__ __launch_bounds__(FPS_THREADS)
void fused_kernel(const float* __restrict__ x, const float* __restrict__ p,
                  const float* __restrict__ Wm, const float* __restrict__ bias,
                  const float* __restrict__ gamma, const float* __restrict__ beta,
                  const float* __restrict__ mean, const float* __restrict__ var,
                  float* __restrict__ out)
{
    extern __shared__ char smem[];
    if (blockIdx.x < 16)
        fps_block(p, out, smem);
    else
        gemm_block(x, Wm, bias, gamma, beta, mean, var, (int)blockIdx.x - 16, smem);
}

// ---------------- gather + maxpool over K neighbors (fp16 h) ----------------
// fp16 rounding is monotonic: max_k rnd(h_k) == rnd(max_k h_k); only one fp16
// rounding of the final max vs fp32 (<= 2^-11 relative).
// sid_euc is int32 in practice (JAX x64 disabled); deterministic int64 sniff kept.
__global__ __launch_bounds__(64)
void gather_kernel(const int* __restrict__ sid32, float* __restrict__ out)
{
    __shared__ int s_idx[KNB];
    const int r = blockIdx.x;     // output row in [0, B*n)
    const int t = threadIdx.x;    // 0..63, channel group: 8 halves at col t*8
    if (t < KNB) {
        const bool is64 = (sid32[1] == 0) && (sid32[3] == 0) &&
                          (sid32[5] == 0) && (sid32[7] == 0);
        const int fidf = g_fid[r];
        s_idx[t] = is64 ? sid32[((size_t)fidf * KNB + t) * 2]
                        : sid32[(size_t)fidf * KNB + t];
    }
    __syncthreads();

    uint4 v = *(const uint4*)(g_h + (size_t)s_idx[0] * COUT + t * 8);
    __half2 m0 = *(__half2*)&v.x, m1 = *(__half2*)&v.y;
    __half2 m2 = *(__half2*)&v.z, m3 = *(__half2*)&v.w;
#pragma unroll
    for (int k = 1; k < KNB; ++k) {
        v = *(const uint4*)(g_h + (size_t)s_idx[k] * COUT + t * 8);
        m0 = __hmax2(m0, *(__half2*)&v.x);
        m1 = __hmax2(m1, *(__half2*)&v.y);
        m2 = __hmax2(m2, *(__half2*)&v.z);
        m3 = __hmax2(m3, *(__half2*)&v.w);
    }
    const float2 f0 = __half22float2(m0), f1 = __half22float2(m1);
    const float2 f2 = __half22float2(m2), f3 = __half22float2(m3);
    float* o = out + (size_t)r * COUT + t * 8;
    *(float4*)(o)     = make_float4(f0.x, f0.y, f1.x, f1.y);
    *(float4*)(o + 4) = make_float4(f2.x, f2.y, f3.x, f3.y);
}

// ---------------- launch ----------------
// 53.5 KB: FPS fits (49152 pts + 256 reduce slab), GEMM fits (37888), and GEMM
// keeps 4 CTAs/SM (4 x 53504 = 214016 < 228KB, 4 x 512 = 2048 threads).
#define FUSED_SMEM 53504

extern "C" void kernel_launch(void* const* d_in, const int* in_sizes, int n_in,
                              void* d_out, int out_size)
{
    (void)in_sizes; (void)n_in; (void)out_size;
    const float* x      = (const float*)d_in[0];
    const float* p      = (const float*)d_in[1];
    const int*   sid    = (const int*)d_in[2];   // int32 (x64 disabled in JAX)
    // d_in[3] = tid_euc (unused by reference)
    const float* W      = (const float*)d_in[4];
    const float* bias   = (const float*)d_in[5];
    const float* gamma  = (const float*)d_in[6];
    const float* beta   = (const float*)d_in[7];
    const float* mean   = (const float*)d_in[8];
    const float* var    = (const float*)d_in[9];
    float* out = (float*)d_out;

    // Opt-in to >48KB dynamic smem (host-side, idempotent, capture-legal).
    cudaFuncSetAttribute(fused_kernel, cudaFuncAttributeMaxDynamicSharedMemorySize, FUSED_SMEM);

    const int gemm_blocks = (BATCH * NPTS / 128) * (COUT / 128);  // 2048
    fused_kernel<<<16 + gemm_blocks, FPS_THREADS, FUSED_SMEM>>>(
        x, p, W, bias, gamma, beta, mean, var, out);
    gather_kernel<<<BATCH * NOUT, 64>>>(sid, out);
}

// round 12
// speedup vs baseline: 1.2502x; 1.0158x over previous
#include <cuda_runtime.h>
#include <cuda_fp16.h>
#include <cstdint>

#define BATCH 16
#define NPTS  4096
#define NOUT  1024
#define CIN   256
#define COUT  512
#define KNB   16
#define XOUT_ELEMS (BATCH * NOUT * COUT)   // 8388608
#define FPS_THREADS 512

#define GEMM_BLOCKS   2048                 // (BATCH*NPTS/128)*(COUT/128)
#define GATHER_ROWS_PER_BLOCK 8
#define GATHER_BLOCKS (BATCH * NOUT / GATHER_ROWS_PER_BLOCK)  // 2048

// Scratch: device globals (no allocation allowed anywhere).
__device__ __half g_h[(size_t)BATCH * NPTS * COUT];  // 64 MB: post-MLP features (fp16)
__device__ int    g_fid[BATCH * NOUT];               // flat FPS indices into B*N
__device__ int    g_prog[BATCH];                     // FPS progress (max published it), reset per run
__device__ int    g_done;                            // # completed GEMM blocks, reset per run

// ---------------- packed f32x2 helpers (bit-exact per-lane .rn) ----------------
static __device__ __forceinline__ unsigned long long pk2(float a, float b) {
    unsigned long long r;
    asm("mov.b64 %0,{%1,%2};" : "=l"(r) : "f"(a), "f"(b));
    return r;
}
static __device__ __forceinline__ void upk2(unsigned long long v, float& a, float& b) {
    asm("mov.b64 {%0,%1},%2;" : "=f"(a), "=f"(b) : "l"(v));
}
static __device__ __forceinline__ unsigned long long addx2(unsigned long long a, unsigned long long b) {
    unsigned long long r;
    asm("add.rn.f32x2 %0,%1,%2;" : "=l"(r) : "l"(a), "l"(b));
    return r;
}
static __device__ __forceinline__ unsigned long long mulx2(unsigned long long a, unsigned long long b) {
    unsigned long long r;
    asm("mul.rn.f32x2 %0,%1,%2;" : "=l"(r) : "l"(a), "l"(b));
    return r;
}
static __device__ __forceinline__ uint32_t f2tf32(float f) {
    uint32_t r;
    asm("cvt.rna.tf32.f32 %0,%1;" : "=r"(r) : "f"(f));
    return r;
}
static __device__ __forceinline__ void mma_tf32(float* c, const uint32_t* a, const uint32_t* b) {
    asm volatile(
        "mma.sync.aligned.m16n8k8.row.col.f32.tf32.tf32.f32 "
        "{%0,%1,%2,%3},{%4,%5,%6,%7},{%8,%9},{%0,%1,%2,%3};"
        : "+f"(c[0]), "+f"(c[1]), "+f"(c[2]), "+f"(c[3])
        : "r"(a[0]), "r"(a[1]), "r"(a[2]), "r"(a[3]), "r"(b[0]), "r"(b[1]));
}

// ---------------- FPS: one CTA (512 threads) per batch ----------------
// Arithmetic/selection bit-identical to the R11 passing kernel:
// dist = ((dx*dx + dy*dy) + dz*dz), all .rn, NO fma contraction; running fmin;
// first-occurrence argmax via strict-> scan + lowest-lane/lowest-warp ties.
// Single barrier per iteration; stage 2 speculatively prefetches candidate
// centers so only value-redux + coord-shfl sit on the serial tail.
// NEW: thread 0 publishes progress (g_prog[b] = it) every 32 iterations with a
// gpu-scope fence, enabling in-grid gather overlap.
static __device__ void fps_block(const float* __restrict__ p, float* __restrict__ out, char* smem)
{
    const int b = blockIdx.x;
    float* s_p  = (float*)smem;                 // 4096*3 floats, interleaved xyz
    float* s_rv = s_p + 3 * NPTS;               // [2 parity][16]
    int*   s_ri = (int*)(s_rv + 32);            // [2 parity][16]

    const float* pb = p + (size_t)b * NPTS * 3;
    const int t = threadIdx.x, lane = t & 31, warp = t >> 5;
    for (int i = t; i < 3 * NPTS; i += FPS_THREADS) s_p[i] = pb[i];
    __syncthreads();

    // it = 0 output (forced index 0)
    if (t == 0) {
        g_fid[b * NOUT] = b * NPTS;
        float* po = out + (size_t)XOUT_ELEMS + (size_t)(b * NOUT) * 3;
        po[0] = s_p[0]; po[1] = s_p[1]; po[2] = s_p[2];
        __threadfence();
        *(volatile int*)&g_prog[b] = 0;          // row i=0 ready
    }

    // thread t owns points [t*8, t*8+8), packed in pairs
    const int base = t * 8;
    unsigned long long Px[4], Py[4], Pz[4];
    float d[8];
#pragma unroll
    for (int q = 0; q < 4; ++q) {
        const int j0 = base + 2 * q;
        Px[q] = pk2(s_p[3 * j0 + 0], s_p[3 * j0 + 3]);
        Py[q] = pk2(s_p[3 * j0 + 1], s_p[3 * j0 + 4]);
        Pz[q] = pk2(s_p[3 * j0 + 2], s_p[3 * j0 + 5]);
    }
#pragma unroll
    for (int j = 0; j < 8; ++j) d[j] = __int_as_float(0x7f800000);  // +inf

    float cx = s_p[0], cy = s_p[1], cz = s_p[2];  // center = point 0

    for (int it = 1; it < NOUT; ++it) {
        const int buf = it & 1;
        const unsigned long long nx = pk2(-cx, -cx);
        const unsigned long long ny = pk2(-cy, -cy);
        const unsigned long long nz = pk2(-cz, -cz);
        float best = -1.0f;
        int bi = base;
#pragma unroll
        for (int q = 0; q < 4; ++q) {
            unsigned long long dx = addx2(Px[q], nx);
            unsigned long long dy = addx2(Py[q], ny);
            unsigned long long dz = addx2(Pz[q], nz);
            unsigned long long sq =
                addx2(addx2(mulx2(dx, dx), mulx2(dy, dy)), mulx2(dz, dz));
            float s0, s1;
            upk2(sq, s0, s1);
            float d0 = fminf(d[2 * q], s0);
            float d1 = fminf(d[2 * q + 1], s1);
            d[2 * q] = d0;
            d[2 * q + 1] = d1;
            if (d0 > best) { best = d0; bi = base + 2 * q; }
            if (d1 > best) { best = d1; bi = base + 2 * q + 1; }
        }
        // warp argmax: d >= 0 so float bits are monotonic as u32
        const unsigned bb = __float_as_uint(best);
        const unsigned wm = __reduce_max_sync(0xffffffffu, bb);
        const unsigned msk = __ballot_sync(0xffffffffu, bb == wm);
        const int src = __ffs(msk) - 1;              // lowest lane = lowest point idx
        const int wbi = __shfl_sync(0xffffffffu, bi, src);
        if (lane == 0) {
            s_rv[buf * 16 + warp] = __uint_as_float(wm);
            s_ri[buf * 16 + warp] = wbi;
        }
        __syncthreads();   // single barrier per iteration

        // stage 2: every warp redundantly reduces the 16 per-warp candidates;
        // speculative center prefetch overlaps the value redux.
        const float* rv = s_rv + buf * 16;
        const int*   ri = s_ri + buf * 16;
        const unsigned v = (lane < 16) ? __float_as_uint(rv[lane]) : 0u;
        const int ril = (lane < 16) ? ri[lane] : 0;
        const float pxl = s_p[3 * ril];
        const float pyl = s_p[3 * ril + 1];
        const float pzl = s_p[3 * ril + 2];
        const unsigned m2 = __reduce_max_sync(0xffffffffu, v);
        const unsigned e2 = __ballot_sync(0xffffffffu, (v == m2) && (lane < 16));
        const int s2 = __ffs(e2) - 1;                // lowest warp = lowest point idx
        cx = __shfl_sync(0xffffffffu, pxl, s2);
        cy = __shfl_sync(0xffffffffu, pyl, s2);
        cz = __shfl_sync(0xffffffffu, pzl, s2);

        if (warp == 0) {
            const int w = __shfl_sync(0xffffffffu, ril, s2);
            if (lane == 0) {
                g_fid[b * NOUT + it] = b * NPTS + w;
                float* po = out + (size_t)XOUT_ELEMS + (size_t)(b * NOUT + it) * 3;
                po[0] = cx; po[1] = cy; po[2] = cz;
                if ((it & 31) == 31) {               // publish every 32 iters (incl. 1023)
                    __threadfence();
                    *(volatile int*)&g_prog[b] = it;
                }
            }
        }
    }
}

// ---------------- GEMM: h = ReLU(BN(x @ W^T + b)), tf32 mma.sync, fp16 out ----------------
// CTA tile 128x128, 512 threads = 16 warps (4x4), warp tile 32x32, K-chunk 32.
static __device__ void gemm_block(const float* __restrict__ x, const float* __restrict__ Wm,
                                  const float* __restrict__ bias, const float* __restrict__ gamma,
                                  const float* __restrict__ beta, const float* __restrict__ mean,
                                  const float* __restrict__ var, int g, char* smem)
{
    float* As   = (float*)smem;        // 128 x 36 (padded)
    float* Bs   = As + 128 * 36;       // 128 x 36
    float* s_sc = Bs + 128 * 36;       // 128
    float* s_sh = s_sc + 128;          // 128

    const int m0 = (g >> 2) * 128;     // 512 M-tiles
    const int n0 = (g & 3) * 128;      // 4 N-tiles
    const int t = threadIdx.x, lane = t & 31, warp = t >> 5;
    const int wm = warp >> 2, wn = warp & 3;
    const int grp = lane >> 2, tg = lane & 3;

    if (t < 128) {
        const int c = n0 + t;
        const float sc = gamma[c] * rsqrtf(var[c] + 1e-5f);
        s_sc[t] = sc;
        s_sh[t] = (bias[c] - mean[c]) * sc + beta[c];
    }

    float acc[2][4][4];
#pragma unroll
    for (int mt = 0; mt < 2; ++mt)
#pragma unroll
        for (int nt = 0; nt < 4; ++nt)
#pragma unroll
            for (int j = 0; j < 4; ++j) acc[mt][nt][j] = 0.0f;

    for (int kc = 0; kc < CIN; kc += 32) {
#pragma unroll
        for (int r = 0; r < 2; ++r) {
            const int fi = t + r * 512;
            const int row = fi >> 3, c4 = (fi & 7) * 4;
            const float4 va = *(const float4*)(x + (size_t)(m0 + row) * CIN + kc + c4);
            *(float4*)(As + row * 36 + c4) = va;
            const float4 vb = *(const float4*)(Wm + (size_t)(n0 + row) * CIN + kc + c4);
            *(float4*)(Bs + row * 36 + c4) = vb;
        }
        __syncthreads();
#pragma unroll
        for (int ks = 0; ks < 4; ++ks) {
            const int kb = ks * 8;
            uint32_t a[2][4], bf[4][2];
#pragma unroll
            for (int mt = 0; mt < 2; ++mt) {
                const float* ap = As + (wm * 32 + mt * 16 + grp) * 36 + kb + tg;
                a[mt][0] = f2tf32(ap[0]);
                a[mt][1] = f2tf32(ap[8 * 36]);
                a[mt][2] = f2tf32(ap[4]);
                a[mt][3] = f2tf32(ap[8 * 36 + 4]);
            }
#pragma unroll
            for (int nt = 0; nt < 4; ++nt) {
                const float* bp = Bs + (wn * 32 + nt * 8 + grp) * 36 + kb + tg;
                bf[nt][0] = f2tf32(bp[0]);
                bf[nt][1] = f2tf32(bp[4]);
            }
#pragma unroll
            for (int mt = 0; mt < 2; ++mt)
#pragma unroll
                for (int nt = 0; nt < 4; ++nt) mma_tf32(acc[mt][nt], a[mt], bf[nt]);
        }
        __syncthreads();
    }

    // epilogue: BN(eval) + ReLU -> fp16 (paired cols => half2 stores)
#pragma unroll
    for (int mt = 0; mt < 2; ++mt) {
#pragma unroll
        for (int nt = 0; nt < 4; ++nt) {
#pragma unroll
            for (int rr = 0; rr < 2; ++rr) {   // rr: +0 / +8 row
                const int row = m0 + wm * 32 + mt * 16 + grp + rr * 8;
                const int lc = wn * 32 + nt * 8 + tg * 2;
                float v0 = acc[mt][nt][rr * 2 + 0] * s_sc[lc]     + s_sh[lc];
                float v1 = acc[mt][nt][rr * 2 + 1] * s_sc[lc + 1] + s_sh[lc + 1];
                v0 = fmaxf(v0, 0.0f);
                v1 = fmaxf(v1, 0.0f);
                *(__half2*)(g_h + (size_t)row * COUT + n0 + lc) = __floats2half2_rn(v0, v1);
            }
        }
    }

    // publish completion (all threads fence their writes, then one atomic)
    __threadfence();
    __syncthreads();
    if (t == 0) atomicAdd(&g_done, 1);
}

// ---------------- gather block: 8 output rows, spin until producers ready ----------------
// fp16 rounding is monotonic: max_k rnd(h_k) == rnd(max_k h_k); only one fp16
// rounding of the final max vs fp32 (<= 2^-11 relative).
// sid_euc is int32 in practice (JAX x64 disabled); deterministic int64 sniff kept.
static __device__ void gather_block(const int* __restrict__ sid32, float* __restrict__ out,
                                    int gb, char* smem)
{
    int* s_idx = (int*)smem;                    // [8][16]
    const int r0 = gb * GATHER_ROWS_PER_BLOCK;  // first output row
    const int b  = r0 >> 10;                    // batch (8 rows never cross a batch)
    const int imax = (r0 & (NOUT - 1)) + GATHER_ROWS_PER_BLOCK - 1;
    const int t = threadIdx.x;

    // wait: all GEMM blocks done AND FPS has published up to imax for batch b
    while (*(volatile int*)&g_done < GEMM_BLOCKS) __nanosleep(256);
    while (*(volatile int*)&g_prog[b] < imax)     __nanosleep(256);
    __threadfence();   // acquire: order subsequent g_fid/g_h loads after the waits

    const int rr = t >> 6;                      // 0..7 local row
    const int c  = t & 63;                      // 0..63 channel group (8 halves)
    if (c < KNB) {
        const bool is64 = (sid32[1] == 0) && (sid32[3] == 0) &&
                          (sid32[5] == 0) && (sid32[7] == 0);
        const int fidf = g_fid[r0 + rr];
        s_idx[rr * KNB + c] = is64 ? sid32[((size_t)fidf * KNB + c) * 2]
                                   : sid32[(size_t)fidf * KNB + c];
    }
    __syncthreads();

    const int* idx = s_idx + rr * KNB;
    uint4 v = *(const uint4*)(g_h + (size_t)idx[0] * COUT + c * 8);
    __half2 m0 = *(__half2*)&v.x, m1 = *(__half2*)&v.y;
    __half2 m2 = *(__half2*)&v.z, m3 = *(__half2*)&v.w;
#pragma unroll
    for (int k = 1; k < KNB; ++k) {
        v = *(const uint4*)(g_h + (size_t)idx[k] * COUT + c * 8);
        m0 = __hmax2(m0, *(__half2*)&v.x);
        m1 = __hmax2(m1, *(__half2*)&v.y);
        m2 = __hmax2(m2, *(__half2*)&v.z);
        m3 = __hmax2(m3, *(__half2*)&v.w);
    }
    const float2 f0 = __half22float2(m0), f1 = __half22float2(m1);
    const float2 f2 = __half22float2(m2), f3 = __half22float2(m3);
    float* o = out + (size_t)(r0 + rr) * COUT + c * 8;
    *(float4*)(o)     = make_float4(f0.x, f0.y, f1.x, f1.y);
    *(float4*)(o + 4) = make_float4(f2.x, f2.y, f3.x, f3.y);
}

// ---------------- init: reset cross-block progress state (replay-safe) ----------------
__global__ void init_kernel()
{
    const int t = threadIdx.x;
    if (t < BATCH) g_prog[t] = -1;
    if (t == BATCH) g_done = 0;
}

// ---- fused kernel: [0,16) FPS | [16,2064) GEMM | [2064,4112) gather overlap ----
// Work distributor issues CTAs in bid order: FPS resident from wave 1, all GEMM
// blocks schedule before any gather block -> gather spins can never starve a
// producer; gather blocks retire progressively as FPS publishes rows.
__global__ __launch_bounds__(FPS_THREADS)
void fused_kernel(const float* __restrict__ x, const float* __restrict__ p,
                  const float* __restrict__ Wm, const float* __restrict__ bias,
                  const float* __restrict__ gamma, const float* __restrict__ beta,
                  const float* __restrict__ mean, const float* __restrict__ var,
                  const int* __restrict__ sid32, float* __restrict__ out)
{
    extern __shared__ char smem[];
    const int bid = blockIdx.x;
    if (bid < 16)
        fps_block(p, out, smem);
    else if (bid < 16 + GEMM_BLOCKS)
        gemm_block(x, Wm, bias, gamma, beta, mean, var, bid - 16, smem);
    else
        gather_block(sid32, out, bid - 16 - GEMM_BLOCKS, smem);
}

// ---------------- launch ----------------
// 53.5 KB: FPS fits (49152 pts + 256 reduce slab), GEMM fits (37888), gather
// needs 512 B; GEMM keeps 4 CTAs/SM (4 x 53504 = 214016 < 228KB).
#define FUSED_SMEM 53504

extern "C" void kernel_launch(void* const* d_in, const int* in_sizes, int n_in,
                              void* d_out, int out_size)
{
    (void)in_sizes; (void)n_in; (void)out_size;
    const float* x      = (const float*)d_in[0];
    const float* p      = (const float*)d_in[1];
    const int*   sid    = (const int*)d_in[2];   // int32 (x64 disabled in JAX)
    // d_in[3] = tid_euc (unused by reference)
    const float* W      = (const float*)d_in[4];
    const float* bias   = (const float*)d_in[5];
    const float* gamma  = (const float*)d_in[6];
    const float* beta   = (const float*)d_in[7];
    const float* mean   = (const float*)d_in[8];
    const float* var    = (const float*)d_in[9];
    float* out = (float*)d_out;

    // Opt-in to >48KB dynamic smem (host-side, idempotent, capture-legal).
    cudaFuncSetAttribute(fused_kernel, cudaFuncAttributeMaxDynamicSharedMemorySize, FUSED_SMEM);

    init_kernel<<<1, 32>>>();
    fused_kernel<<<16 + GEMM_BLOCKS + GATHER_BLOCKS, FPS_THREADS, FUSED_SMEM>>>(
        x, p, W, bias, gamma, beta, mean, var, sid, out);
}